// round 1
// baseline (speedup 1.0000x reference)
#include <cuda_runtime.h>
#include <cstdint>

#define N_NODES  50000
#define N_EDGES  500000
#define DIM      128
#define N_GRAPHS 256

// ---------------- scratch (device globals: allocation-free) ----------------
__device__ __align__(16) float g_m [N_NODES * DIM];  // messages  h @ W_rel^T
__device__ __align__(16) float g_h1[N_NODES * DIM];  // layer1 pre-relu (root + bias + agg)
__device__ __align__(16) float g_h2[N_NODES * DIM];  // layer2 pre-relu
__device__ int g_cnt[N_GRAPHS];
__device__ int g_is64;

// ---------------- int32/int64 index-width detection ----------------
// jnp.int64 canonicalizes to int32 unless x64 is enabled; detect on device.
// int64 little-endian values < 2^31  ->  every odd 32-bit word is 0.
__global__ void detect_kernel(const unsigned* __restrict__ ew) {
    if (threadIdx.x == 0) {
        unsigned o = 0;
#pragma unroll
        for (int k = 1; k < 64; k += 2) o |= ew[k];
        g_is64 = (o == 0) ? 1 : 0;
    }
}

__device__ __forceinline__ int ld_idx(const void* p, long long i, int is64) {
    if (is64) return (int)((const long long*)p)[i];
    return ((const int*)p)[i];
}

// ---------------- dual GEMM: M = relu?(X) @ Wrel^T ; H = relu?(X) @ Wroot^T + b ----------
// gridDim = (391, 2): blockIdx.y == 0 -> Wrel->M, == 1 -> Wroot(+bias)->H
// layer: 0 -> X = x input (no relu), out {g_m, g_h1}
//        1 -> X = relu(g_h1),        out {g_m, g_h2}
__global__ __launch_bounds__(256) void gemm_dual(
    const float* __restrict__ Xin,
    const float* __restrict__ Wrel, const float* __restrict__ Wroot,
    const float* __restrict__ bias, int layer)
{
    __shared__ float As[16][128];
    __shared__ float Bs[16][128];

    const int tid = threadIdx.x;
    const int tx = tid & 15;   // col group (8 cols each)
    const int ty = tid >> 4;   // row group (8 rows each)
    const int row0 = blockIdx.x * 128;
    const bool isRoot = (blockIdx.y == 1);
    const int reluIn = layer;

    const float* __restrict__ X = (layer == 0) ? Xin : g_h1;
    const float* __restrict__ W = isRoot ? Wroot : Wrel;
    float* __restrict__ Out = isRoot ? ((layer == 0) ? g_h1 : g_h2) : g_m;

    float acc[8][8];
#pragma unroll
    for (int i = 0; i < 8; i++)
#pragma unroll
        for (int j = 0; j < 8; j++) acc[i][j] = 0.f;

    for (int kc = 0; kc < DIM; kc += 16) {
#pragma unroll
        for (int i = 0; i < 2; i++) {
            int idx = tid * 2 + i;          // 0..511
            int r   = idx >> 2;             // 0..127
            int c4  = (idx & 3) * 4;        // k sub-offset {0,4,8,12}
            int grow = row0 + r;
            float4 v = make_float4(0.f, 0.f, 0.f, 0.f);
            if (grow < N_NODES)
                v = *(const float4*)(X + (size_t)grow * DIM + kc + c4);
            if (reluIn) {
                v.x = fmaxf(v.x, 0.f); v.y = fmaxf(v.y, 0.f);
                v.z = fmaxf(v.z, 0.f); v.w = fmaxf(v.w, 0.f);
            }
            As[c4 + 0][r] = v.x; As[c4 + 1][r] = v.y;
            As[c4 + 2][r] = v.z; As[c4 + 3][r] = v.w;
            // W is [128 out, 128 k] row-major; r doubles as output column index
            float4 w4 = *(const float4*)(W + (size_t)r * DIM + kc + c4);
            Bs[c4 + 0][r] = w4.x; Bs[c4 + 1][r] = w4.y;
            Bs[c4 + 2][r] = w4.z; Bs[c4 + 3][r] = w4.w;
        }
        __syncthreads();
#pragma unroll
        for (int k = 0; k < 16; k++) {
            float a[8], b[8];
            *(float4*)&a[0] = *(const float4*)&As[k][ty * 8];
            *(float4*)&a[4] = *(const float4*)&As[k][ty * 8 + 4];
            *(float4*)&b[0] = *(const float4*)&Bs[k][tx * 8];
            *(float4*)&b[4] = *(const float4*)&Bs[k][tx * 8 + 4];
#pragma unroll
            for (int i = 0; i < 8; i++)
#pragma unroll
                for (int j = 0; j < 8; j++)
                    acc[i][j] = fmaf(a[i], b[j], acc[i][j]);
        }
        __syncthreads();
    }

    float bb[8];
#pragma unroll
    for (int j = 0; j < 8; j++) bb[j] = isRoot ? bias[tx * 8 + j] : 0.f;

#pragma unroll
    for (int i = 0; i < 8; i++) {
        int grow = row0 + ty * 8 + i;
        if (grow >= N_NODES) continue;
        float4 o0 = make_float4(acc[i][0] + bb[0], acc[i][1] + bb[1],
                                acc[i][2] + bb[2], acc[i][3] + bb[3]);
        float4 o1 = make_float4(acc[i][4] + bb[4], acc[i][5] + bb[5],
                                acc[i][6] + bb[6], acc[i][7] + bb[7]);
        *(float4*)(Out + (size_t)grow * DIM + tx * 8)     = o0;
        *(float4*)(Out + (size_t)grow * DIM + tx * 8 + 4) = o1;
    }
}

// ---------------- edge scatter: H[dst] += M[src], warp per edge, float4 red ----------
__global__ __launch_bounds__(256) void scatter_kernel(const void* __restrict__ edges, int layer)
{
    const int is64 = g_is64;
    const int lane = threadIdx.x & 31;
    const float4* __restrict__ M = (const float4*)g_m;
    float* __restrict__ H = layer ? g_h2 : g_h1;
    int warp = (blockIdx.x * blockDim.x + threadIdx.x) >> 5;
    const int nw = (gridDim.x * blockDim.x) >> 5;
    for (int e = warp; e < N_EDGES; e += nw) {
        int src = ld_idx(edges, e, is64);
        int dst = ld_idx(edges, (long long)N_EDGES + e, is64);
        float4 v = M[(size_t)src * (DIM / 4) + lane];
        atomicAdd((float4*)(H + (size_t)dst * DIM + lane * 4), v);
    }
}

// ---------------- epilogue: counts, init, pooled dot ----------------
__global__ void init_kernel(float* __restrict__ out, const float* __restrict__ b_out) {
    int t = threadIdx.x;
    if (t < N_GRAPHS) { g_cnt[t] = 0; out[t] = b_out[0]; }
}

__global__ void count_kernel(const void* __restrict__ batch) {
    int i = blockIdx.x * blockDim.x + threadIdx.x;
    if (i < N_NODES) atomicAdd(&g_cnt[ld_idx(batch, i, g_is64)], 1);
}

__global__ __launch_bounds__(256) void pool_kernel(const void* __restrict__ batch,
                                                   const float* __restrict__ Wout,
                                                   float* __restrict__ out)
{
    const int is64 = g_is64;
    const int lane = threadIdx.x & 31;
    int warp = (blockIdx.x * blockDim.x + threadIdx.x) >> 5;
    const int nw = (gridDim.x * blockDim.x) >> 5;
    for (int i = warp; i < N_NODES; i += nw) {
        float s = 0.f;
#pragma unroll
        for (int q = 0; q < 4; q++) {
            int c = lane + q * 32;
            s = fmaf(fmaxf(g_h2[(size_t)i * DIM + c], 0.f), Wout[c], s);
        }
#pragma unroll
        for (int o = 16; o; o >>= 1) s += __shfl_xor_sync(0xffffffffu, s, o);
        if (lane == 0) {
            int g = ld_idx(batch, i, is64);
            int c = g_cnt[g]; if (c < 1) c = 1;
            atomicAdd(&out[g], s / (float)c);
        }
    }
}

// ---------------- launcher ----------------
extern "C" void kernel_launch(void* const* d_in, const int* in_sizes, int n_in,
                              void* d_out, int out_size) {
    const float* x       = (const float*)d_in[0];
    const void*  edges   = d_in[1];
    const void*  batch   = d_in[2];
    const float* W1_rel  = (const float*)d_in[3];
    const float* W1_root = (const float*)d_in[4];
    const float* b1      = (const float*)d_in[5];
    const float* W2_rel  = (const float*)d_in[6];
    const float* W2_root = (const float*)d_in[7];
    const float* b2      = (const float*)d_in[8];
    const float* W_out   = (const float*)d_in[9];
    const float* b_out   = (const float*)d_in[10];
    float* out = (float*)d_out;

    const dim3 gemmGrid((N_NODES + 127) / 128, 2);

    detect_kernel<<<1, 32>>>((const unsigned*)edges);

    gemm_dual<<<gemmGrid, 256>>>(x, W1_rel, W1_root, b1, 0);
    scatter_kernel<<<2048, 256>>>(edges, 0);

    gemm_dual<<<gemmGrid, 256>>>(x, W2_rel, W2_root, b2, 1);
    scatter_kernel<<<2048, 256>>>(edges, 1);

    init_kernel<<<1, 256>>>(out, b_out);
    count_kernel<<<(N_NODES + 255) / 256, 256>>>(batch);
    pool_kernel<<<2048, 256>>>(batch, W_out, out);
}

// round 3
// speedup vs baseline: 1.3706x; 1.3706x over previous
#include <cuda_runtime.h>
#include <cuda_bf16.h>
#include <cstdint>

#define N_NODES  50000
#define N_EDGES  500000
#define DIM      128
#define N_GRAPHS 256

// ---------------- scratch (device globals: allocation-free) ----------------
__device__ __align__(16) float g_m [N_NODES * DIM];  // messages  h @ W_rel^T
__device__ __align__(16) float g_h1[N_NODES * DIM];  // layer1 pre-relu
__device__ __align__(16) float g_h2[N_NODES * DIM];  // layer2 pre-relu
__device__ int g_cnt[N_GRAPHS];
__device__ int g_is64;

// ---------------- helpers ----------------
__device__ __forceinline__ uint32_t smem_u32(const void* p) {
    uint32_t a;
    asm("{ .reg .u64 t; cvta.to.shared.u64 t, %1; cvt.u32.u64 %0, t; }" : "=r"(a) : "l"(p));
    return a;
}

// ---------------- int32/int64 index-width detection ----------------
__global__ void detect_kernel(const unsigned* __restrict__ ew) {
    if (threadIdx.x == 0) {
        unsigned o = 0;
#pragma unroll
        for (int k = 1; k < 64; k += 2) o |= ew[k];
        g_is64 = (o == 0) ? 1 : 0;
    }
}
__device__ __forceinline__ int ld_idx(const void* p, long long i, int is64) {
    if (is64) return (int)((const long long*)p)[i];
    return ((const int*)p)[i];
}

// ---------------- bf16 hi/lo conversion ----------------
__device__ __forceinline__ void cvt8(float4 v0, float4 v1, uint4& hi, uint4& lo) {
    float f[8] = {v0.x, v0.y, v0.z, v0.w, v1.x, v1.y, v1.z, v1.w};
    uint32_t h[4], l[4];
#pragma unroll
    for (int i = 0; i < 4; i++) {
        float a = f[2 * i], b = f[2 * i + 1];
        __nv_bfloat16 ha = __float2bfloat16_rn(a), hb = __float2bfloat16_rn(b);
        __nv_bfloat162 hp; hp.x = ha; hp.y = hb;
        __nv_bfloat162 lp = __floats2bfloat162_rn(a - __bfloat162float(ha),
                                                  b - __bfloat162float(hb));
        h[i] = *reinterpret_cast<uint32_t*>(&hp);
        l[i] = *reinterpret_cast<uint32_t*>(&lp);
    }
    hi = make_uint4(h[0], h[1], h[2], h[3]);
    lo = make_uint4(l[0], l[1], l[2], l[3]);
}
__device__ __forceinline__ void sts128(uint32_t addr, uint4 v) {
    asm volatile("st.shared.v4.b32 [%0], {%1,%2,%3,%4};"
                 :: "r"(addr), "r"(v.x), "r"(v.y), "r"(v.z), "r"(v.w) : "memory");
}

// ---------------- mma.sync bf16 GEMM (HMMA, no tcgen05 needed) ----------------
// Out[m,n] = sum_k X[m,k] * W[n,k]   (row.col layout: A row-major, B = W rows)
// CTA tile 128x128, 8 warps (2x4), warp tile 64x32, mma m16n8k16.
// bf16 hi/lo split, 3 accumulation passes (hh, lh, hl) into fp32 regs.
// SMEM: A hi/lo + B hi/lo, 128 rows x 136 bf16 pitch (272B, ldmatrix conflict-free)
#define PITCH_E 136
#define PITCH_B 272
#define MAT_SZ  (128 * PITCH_B)       // 34816 bytes
#define SMEM_BYTES (4 * MAT_SZ)       // 139264

__device__ __forceinline__ void ldsm_x4(uint32_t* r, uint32_t addr) {
    asm volatile("ldmatrix.sync.aligned.m8n8.x4.shared.b16 {%0,%1,%2,%3}, [%4];"
                 : "=r"(r[0]), "=r"(r[1]), "=r"(r[2]), "=r"(r[3]) : "r"(addr));
}
__device__ __forceinline__ void mma16816(float* d, const uint32_t* a, const uint32_t* b) {
    asm volatile(
        "mma.sync.aligned.m16n8k16.row.col.f32.bf16.bf16.f32 "
        "{%0,%1,%2,%3}, {%4,%5,%6,%7}, {%8,%9}, {%0,%1,%2,%3};"
        : "+f"(d[0]), "+f"(d[1]), "+f"(d[2]), "+f"(d[3])
        : "r"(a[0]), "r"(a[1]), "r"(a[2]), "r"(a[3]), "r"(b[0]), "r"(b[1]));
}

__global__ __launch_bounds__(256, 1) void gemm_mma(
    const float* __restrict__ Xin,
    const float* __restrict__ Wrel, const float* __restrict__ Wroot,
    const float* __restrict__ bias, int layer)
{
    extern __shared__ char smem[];
    const uint32_t sA = smem_u32(smem);            // A hi at 0, lo at MAT_SZ
    const uint32_t sB = sA + 2 * MAT_SZ;           // B hi, lo
    const int tid = threadIdx.x;
    const int wid = tid >> 5;
    const int lane = tid & 31;
    const int row0 = blockIdx.x * 128;
    const bool isRoot = (blockIdx.y == 1);

    const float* __restrict__ X = (layer == 0) ? Xin : g_h1;
    const float* __restrict__ W = isRoot ? Wroot : Wrel;
    float* __restrict__ Out = isRoot ? ((layer == 0) ? g_h1 : g_h2) : g_m;

    // ---- load + convert X tile (128x128) and W (128x128) ----
#pragma unroll
    for (int i = 0; i < 8; i++) {
        int g = tid + i * 256;                 // 0..2047
        int row = g >> 4;
        int e0 = (g & 15) * 8;
        int grow = row0 + row;
        float4 v0 = make_float4(0.f, 0.f, 0.f, 0.f), v1 = v0;
        if (grow < N_NODES) {
            v0 = *(const float4*)(X + (size_t)grow * DIM + e0);
            v1 = *(const float4*)(X + (size_t)grow * DIM + e0 + 4);
        }
        if (layer) {
            v0.x = fmaxf(v0.x, 0.f); v0.y = fmaxf(v0.y, 0.f);
            v0.z = fmaxf(v0.z, 0.f); v0.w = fmaxf(v0.w, 0.f);
            v1.x = fmaxf(v1.x, 0.f); v1.y = fmaxf(v1.y, 0.f);
            v1.z = fmaxf(v1.z, 0.f); v1.w = fmaxf(v1.w, 0.f);
        }
        uint4 hi, lo; cvt8(v0, v1, hi, lo);
        uint32_t off = (uint32_t)(row * PITCH_B + e0 * 2);
        sts128(sA + off, hi);
        sts128(sA + MAT_SZ + off, lo);

        // W tile (same index pattern)
        float4 w0 = *(const float4*)(W + (size_t)row * DIM + e0);
        float4 w1 = *(const float4*)(W + (size_t)row * DIM + e0 + 4);
        uint4 whi, wlo; cvt8(w0, w1, whi, wlo);
        sts128(sB + off, whi);
        sts128(sB + MAT_SZ + off, wlo);
    }
    __syncthreads();

    // ---- warp tiling: 2 (M) x 4 (N) warps; warp tile 64x32 ----
    const int wm = wid >> 2;                   // 0..1  -> m offset wm*64
    const int wn = wid & 3;                    // 0..3  -> n offset wn*32
    const int t4 = lane >> 2;                  // 0..7
    const int t2 = (lane & 3) * 2;

    float d[4][4][4];
#pragma unroll
    for (int i = 0; i < 4; i++)
#pragma unroll
        for (int j = 0; j < 4; j++)
#pragma unroll
            for (int q = 0; q < 4; q++) d[i][j][q] = 0.f;

    const uint32_t aRowOff = (uint32_t)((lane & 15) * PITCH_B + (lane >> 4) * 16);
    const uint32_t bRowOff = (uint32_t)((wn * 32 + (lane & 7) + (lane >> 4) * 8) * PITCH_B
                                        + ((lane >> 3) & 1) * 16);

    const int paA[3] = {0, 1, 0};
    const int paB[3] = {0, 0, 1};
#pragma unroll
    for (int p = 0; p < 3; p++) {
        const uint32_t Ab = sA + paA[p] * MAT_SZ;
        const uint32_t Bb = sB + paB[p] * MAT_SZ;
#pragma unroll
        for (int ks = 0; ks < 8; ks++) {
            uint32_t a[4][4];
#pragma unroll
            for (int i = 0; i < 4; i++)
                ldsm_x4(a[i], Ab + (uint32_t)((wm * 64 + i * 16) * PITCH_B + ks * 32) + aRowOff);
            uint32_t bf[4][2];
#pragma unroll
            for (int jp = 0; jp < 2; jp++) {
                uint32_t r[4];
                ldsm_x4(r, Bb + (uint32_t)(jp * 16 * PITCH_B + ks * 32) + bRowOff);
                bf[jp * 2 + 0][0] = r[0]; bf[jp * 2 + 0][1] = r[1];
                bf[jp * 2 + 1][0] = r[2]; bf[jp * 2 + 1][1] = r[3];
            }
#pragma unroll
            for (int i = 0; i < 4; i++)
#pragma unroll
                for (int j = 0; j < 4; j++)
                    mma16816(d[i][j], a[i], bf[j]);
        }
    }

    // ---- epilogue: regs -> global (float2 stores), bias for root half ----
#pragma unroll
    for (int i = 0; i < 4; i++) {
#pragma unroll
        for (int half = 0; half < 2; half++) {
            int grow = row0 + wm * 64 + i * 16 + t4 + half * 8;
            if (grow >= N_NODES) continue;
#pragma unroll
            for (int j = 0; j < 4; j++) {
                int col = wn * 32 + j * 8 + t2;
                float2 v = make_float2(d[i][j][half * 2], d[i][j][half * 2 + 1]);
                if (isRoot) { v.x += bias[col]; v.y += bias[col + 1]; }
                *(float2*)(Out + (size_t)grow * DIM + col) = v;
            }
        }
    }
}

// ---------------- edge scatter: H[dst] += M[src], warp per edge ----------------
__global__ __launch_bounds__(256) void scatter_kernel(const void* __restrict__ edges, int layer)
{
    const int is64 = g_is64;
    const int lane = threadIdx.x & 31;
    const float4* __restrict__ M = (const float4*)g_m;
    float* __restrict__ H = layer ? g_h2 : g_h1;
    int warp = (blockIdx.x * blockDim.x + threadIdx.x) >> 5;
    const int nw = (gridDim.x * blockDim.x) >> 5;
    for (int e = warp; e < N_EDGES; e += nw) {
        int src = ld_idx(edges, e, is64);
        int dst = ld_idx(edges, (long long)N_EDGES + e, is64);
        float4 v = M[(size_t)src * (DIM / 4) + lane];
        atomicAdd((float4*)(H + (size_t)dst * DIM + lane * 4), v);
    }
}

// ---------------- epilogue: counts, init, pooled dot ----------------
__global__ void init_kernel(float* __restrict__ out, const float* __restrict__ b_out) {
    int t = threadIdx.x;
    if (t < N_GRAPHS) { g_cnt[t] = 0; out[t] = b_out[0]; }
}
__global__ void count_kernel(const void* __restrict__ batch) {
    int i = blockIdx.x * blockDim.x + threadIdx.x;
    if (i < N_NODES) atomicAdd(&g_cnt[ld_idx(batch, i, g_is64)], 1);
}
__global__ __launch_bounds__(256) void pool_kernel(const void* __restrict__ batch,
                                                   const float* __restrict__ Wout,
                                                   float* __restrict__ out)
{
    const int is64 = g_is64;
    const int lane = threadIdx.x & 31;
    int warp = (blockIdx.x * blockDim.x + threadIdx.x) >> 5;
    const int nw = (gridDim.x * blockDim.x) >> 5;
    for (int i = warp; i < N_NODES; i += nw) {
        float s = 0.f;
#pragma unroll
        for (int q = 0; q < 4; q++) {
            int c = lane + q * 32;
            s = fmaf(fmaxf(g_h2[(size_t)i * DIM + c], 0.f), Wout[c], s);
        }
#pragma unroll
        for (int o = 16; o; o >>= 1) s += __shfl_xor_sync(0xffffffffu, s, o);
        if (lane == 0) {
            int g = ld_idx(batch, i, is64);
            int c = g_cnt[g]; if (c < 1) c = 1;
            atomicAdd(&out[g], s / (float)c);
        }
    }
}

// ---------------- launcher ----------------
extern "C" void kernel_launch(void* const* d_in, const int* in_sizes, int n_in,
                              void* d_out, int out_size) {
    const float* x       = (const float*)d_in[0];
    const void*  edges   = d_in[1];
    const void*  batch   = d_in[2];
    const float* W1_rel  = (const float*)d_in[3];
    const float* W1_root = (const float*)d_in[4];
    const float* b1      = (const float*)d_in[5];
    const float* W2_rel  = (const float*)d_in[6];
    const float* W2_root = (const float*)d_in[7];
    const float* b2      = (const float*)d_in[8];
    const float* W_out   = (const float*)d_in[9];
    const float* b_out   = (const float*)d_in[10];
    float* out = (float*)d_out;

    cudaFuncSetAttribute(gemm_mma, cudaFuncAttributeMaxDynamicSharedMemorySize, SMEM_BYTES);

    const dim3 gemmGrid((N_NODES + 127) / 128, 2);   // (391, 2)

    detect_kernel<<<1, 32>>>((const unsigned*)edges);

    gemm_mma<<<gemmGrid, 256, SMEM_BYTES>>>(x, W1_rel, W1_root, b1, 0);
    scatter_kernel<<<2048, 256>>>(edges, 0);

    gemm_mma<<<gemmGrid, 256, SMEM_BYTES>>>(x, W2_rel, W2_root, b2, 1);
    scatter_kernel<<<2048, 256>>>(edges, 1);

    init_kernel<<<1, 256>>>(out, b_out);
    count_kernel<<<(N_NODES + 255) / 256, 256>>>(batch);
    pool_kernel<<<2048, 256>>>(batch, W_out, out);
}

// round 5
// speedup vs baseline: 1.5368x; 1.1213x over previous
#include <cuda_runtime.h>
#include <cuda_bf16.h>
#include <cstdint>

#define N_NODES  50000
#define N_EDGES  500000
#define DIM      128
#define N_GRAPHS 256
#define SCAN_N   (N_NODES + 1)
#define SCAN_BLKS 49   // ceil(50001/1024)

// ---------------- scratch (device globals: allocation-free) ----------------
__device__ __align__(16) float g_m [N_NODES * DIM];  // messages  h @ W_rel^T
__device__ __align__(16) float g_h1[N_NODES * DIM];  // layer1 pre-relu
__device__ __align__(16) float g_h2[N_NODES * DIM];  // layer2 root+bias part
__device__ int g_cnt[N_GRAPHS];
__device__ int g_is64;
// CSR (by destination)
__device__ int g_rowptr[SCAN_N];
__device__ int g_cursor[N_NODES];
__device__ int g_srcs[N_EDGES];
__device__ int g_bsum[SCAN_BLKS];

// ---------------- helpers ----------------
__device__ __forceinline__ uint32_t smem_u32(const void* p) {
    uint32_t a;
    asm("{ .reg .u64 t; cvta.to.shared.u64 t, %1; cvt.u32.u64 %0, t; }" : "=r"(a) : "l"(p));
    return a;
}
__global__ void detect_kernel(const unsigned* __restrict__ ew) {
    if (threadIdx.x == 0) {
        unsigned o = 0;
#pragma unroll
        for (int k = 1; k < 64; k += 2) o |= ew[k];
        g_is64 = (o == 0) ? 1 : 0;
    }
}
__device__ __forceinline__ int ld_idx(const void* p, long long i, int is64) {
    if (is64) return (int)((const long long*)p)[i];
    return ((const int*)p)[i];
}

// ---------------- CSR build ----------------
__global__ void zero_csr_kernel() {
    int i = blockIdx.x * blockDim.x + threadIdx.x;
    if (i < SCAN_N) g_rowptr[i] = 0;
    if (i < N_NODES) g_cursor[i] = 0;
}
__global__ void hist_kernel(const void* __restrict__ edges) {
    int e = blockIdx.x * blockDim.x + threadIdx.x;
    if (e < N_EDGES) {
        int dst = ld_idx(edges, (long long)N_EDGES + e, g_is64);
        atomicAdd(&g_rowptr[dst + 1], 1);
    }
}
__global__ __launch_bounds__(1024) void scan1_kernel() {
    __shared__ int sd[1024];
    int gid = blockIdx.x * 1024 + threadIdx.x;
    int v = (gid < SCAN_N) ? g_rowptr[gid] : 0;
    sd[threadIdx.x] = v;
    __syncthreads();
#pragma unroll
    for (int off = 1; off < 1024; off <<= 1) {
        int t = (threadIdx.x >= off) ? sd[threadIdx.x - off] : 0;
        __syncthreads();
        sd[threadIdx.x] += t;
        __syncthreads();
    }
    if (gid < SCAN_N) g_rowptr[gid] = sd[threadIdx.x];
    if (threadIdx.x == 1023) g_bsum[blockIdx.x] = sd[1023];
}
__global__ void scan2_kernel() {
    if (threadIdx.x == 0) {
        int run = 0;
        for (int i = 0; i < SCAN_BLKS; i++) { int t = g_bsum[i]; g_bsum[i] = run; run += t; }
    }
}
__global__ __launch_bounds__(1024) void scan3_kernel() {
    int gid = blockIdx.x * 1024 + threadIdx.x;
    if (gid < SCAN_N && blockIdx.x > 0) g_rowptr[gid] += g_bsum[blockIdx.x];
}
__global__ void fill_kernel(const void* __restrict__ edges) {
    int e = blockIdx.x * blockDim.x + threadIdx.x;
    if (e < N_EDGES) {
        int is64 = g_is64;
        int src = ld_idx(edges, e, is64);
        int dst = ld_idx(edges, (long long)N_EDGES + e, is64);
        int pos = g_rowptr[dst] + atomicAdd(&g_cursor[dst], 1);
        g_srcs[pos] = src;
    }
}

// ---------------- bf16 hi/lo conversion ----------------
__device__ __forceinline__ void cvt8(float4 v0, float4 v1, uint4& hi, uint4& lo) {
    float f[8] = {v0.x, v0.y, v0.z, v0.w, v1.x, v1.y, v1.z, v1.w};
    uint32_t h[4], l[4];
#pragma unroll
    for (int i = 0; i < 4; i++) {
        float a = f[2 * i], b = f[2 * i + 1];
        __nv_bfloat16 ha = __float2bfloat16_rn(a), hb = __float2bfloat16_rn(b);
        __nv_bfloat162 hp; hp.x = ha; hp.y = hb;
        __nv_bfloat162 lp = __floats2bfloat162_rn(a - __bfloat162float(ha),
                                                  b - __bfloat162float(hb));
        h[i] = *reinterpret_cast<uint32_t*>(&hp);
        l[i] = *reinterpret_cast<uint32_t*>(&lp);
    }
    hi = make_uint4(h[0], h[1], h[2], h[3]);
    lo = make_uint4(l[0], l[1], l[2], l[3]);
}
__device__ __forceinline__ void sts128(uint32_t addr, uint4 v) {
    asm volatile("st.shared.v4.b32 [%0], {%1,%2,%3,%4};"
                 :: "r"(addr), "r"(v.x), "r"(v.y), "r"(v.z), "r"(v.w) : "memory");
}

// ---------------- mma.sync bf16 GEMM (64x128 tile, 2 CTAs/SM) ----------------
#define PITCH_B 272
#define A_SZ    (64 * PITCH_B)        // 17408
#define B_SZ    (128 * PITCH_B)       // 34816
#define SMEM_BYTES (2 * A_SZ + 2 * B_SZ)   // 104448

__device__ __forceinline__ void ldsm_x4(uint32_t* r, uint32_t addr) {
    asm volatile("ldmatrix.sync.aligned.m8n8.x4.shared.b16 {%0,%1,%2,%3}, [%4];"
                 : "=r"(r[0]), "=r"(r[1]), "=r"(r[2]), "=r"(r[3]) : "r"(addr));
}
__device__ __forceinline__ void mma16816(float* d, const uint32_t* a, const uint32_t* b) {
    asm volatile(
        "mma.sync.aligned.m16n8k16.row.col.f32.bf16.bf16.f32 "
        "{%0,%1,%2,%3}, {%4,%5,%6,%7}, {%8,%9}, {%0,%1,%2,%3};"
        : "+f"(d[0]), "+f"(d[1]), "+f"(d[2]), "+f"(d[3])
        : "r"(a[0]), "r"(a[1]), "r"(a[2]), "r"(a[3]), "r"(b[0]), "r"(b[1]));
}

__global__ __launch_bounds__(256, 2) void gemm_mma(
    const float* __restrict__ Xin,
    const float* __restrict__ Wrel, const float* __restrict__ Wroot,
    const float* __restrict__ bias, int layer)
{
    extern __shared__ char smem[];
    const uint32_t sA = smem_u32(smem);            // A hi, A lo
    const uint32_t sB = sA + 2 * A_SZ;             // B hi, B lo
    const int tid = threadIdx.x;
    const int wid = tid >> 5;
    const int lane = tid & 31;
    const int row0 = blockIdx.x * 64;
    const bool isRoot = (blockIdx.y == 1);

    const float* __restrict__ X = (layer == 0) ? Xin : g_h1;
    const float* __restrict__ W = isRoot ? Wroot : Wrel;
    float* __restrict__ Out = isRoot ? ((layer == 0) ? g_h1 : g_h2) : g_m;

    // ---- A tile: 64 x 128 fp32 -> hi/lo bf16 ----
#pragma unroll
    for (int i = 0; i < 4; i++) {
        int g = tid + i * 256;                 // 0..1023
        int row = g >> 4;                      // 0..63
        int e0 = (g & 15) * 8;
        int grow = row0 + row;
        float4 v0 = make_float4(0.f, 0.f, 0.f, 0.f), v1 = v0;
        if (grow < N_NODES) {
            v0 = *(const float4*)(X + (size_t)grow * DIM + e0);
            v1 = *(const float4*)(X + (size_t)grow * DIM + e0 + 4);
        }
        if (layer) {
            v0.x = fmaxf(v0.x, 0.f); v0.y = fmaxf(v0.y, 0.f);
            v0.z = fmaxf(v0.z, 0.f); v0.w = fmaxf(v0.w, 0.f);
            v1.x = fmaxf(v1.x, 0.f); v1.y = fmaxf(v1.y, 0.f);
            v1.z = fmaxf(v1.z, 0.f); v1.w = fmaxf(v1.w, 0.f);
        }
        uint4 hi, lo; cvt8(v0, v1, hi, lo);
        uint32_t off = (uint32_t)(row * PITCH_B + e0 * 2);
        sts128(sA + off, hi);
        sts128(sA + A_SZ + off, lo);
    }
    // ---- B: full W 128 x 128 ----
#pragma unroll
    for (int i = 0; i < 8; i++) {
        int g = tid + i * 256;                 // 0..2047
        int row = g >> 4;                      // 0..127
        int e0 = (g & 15) * 8;
        float4 w0 = *(const float4*)(W + (size_t)row * DIM + e0);
        float4 w1 = *(const float4*)(W + (size_t)row * DIM + e0 + 4);
        uint4 whi, wlo; cvt8(w0, w1, whi, wlo);
        uint32_t off = (uint32_t)(row * PITCH_B + e0 * 2);
        sts128(sB + off, whi);
        sts128(sB + B_SZ + off, wlo);
    }
    __syncthreads();

    // ---- warp tiling: 2 (M) x 4 (N); warp tile 32x32 ----
    const int wm = wid >> 2;
    const int wn = wid & 3;
    const int t4 = lane >> 2;
    const int t2 = (lane & 3) * 2;

    float d[2][4][4];
#pragma unroll
    for (int i = 0; i < 2; i++)
#pragma unroll
        for (int j = 0; j < 4; j++)
#pragma unroll
            for (int q = 0; q < 4; q++) d[i][j][q] = 0.f;

    const uint32_t aRowOff = (uint32_t)((lane & 15) * PITCH_B + (lane >> 4) * 16);
    const uint32_t bRowOff = (uint32_t)((wn * 32 + (lane & 7) + (lane >> 4) * 8) * PITCH_B
                                        + ((lane >> 3) & 1) * 16);

    const int paA[3] = {0, 1, 0};
    const int paB[3] = {0, 0, 1};
#pragma unroll
    for (int p = 0; p < 3; p++) {
        const uint32_t Ab = sA + paA[p] * A_SZ;
        const uint32_t Bb = sB + paB[p] * B_SZ;
#pragma unroll
        for (int ks = 0; ks < 8; ks++) {
            uint32_t a[2][4];
#pragma unroll
            for (int i = 0; i < 2; i++)
                ldsm_x4(a[i], Ab + (uint32_t)((wm * 32 + i * 16) * PITCH_B + ks * 32) + aRowOff);
            uint32_t bf[4][2];
#pragma unroll
            for (int jp = 0; jp < 2; jp++) {
                uint32_t r[4];
                ldsm_x4(r, Bb + (uint32_t)(jp * 16 * PITCH_B + ks * 32) + bRowOff);
                bf[jp * 2 + 0][0] = r[0]; bf[jp * 2 + 0][1] = r[1];
                bf[jp * 2 + 1][0] = r[2]; bf[jp * 2 + 1][1] = r[3];
            }
#pragma unroll
            for (int i = 0; i < 2; i++)
#pragma unroll
                for (int j = 0; j < 4; j++)
                    mma16816(d[i][j], a[i], bf[j]);
        }
    }

    // ---- epilogue ----
#pragma unroll
    for (int i = 0; i < 2; i++) {
#pragma unroll
        for (int half = 0; half < 2; half++) {
            int grow = row0 + wm * 32 + i * 16 + t4 + half * 8;
            if (grow >= N_NODES) continue;
#pragma unroll
            for (int j = 0; j < 4; j++) {
                int col = wn * 32 + j * 8 + t2;
                float2 v = make_float2(d[i][j][half * 2], d[i][j][half * 2 + 1]);
                if (isRoot) { v.x += bias[col]; v.y += bias[col + 1]; }
                *(float2*)(Out + (size_t)grow * DIM + col) = v;
            }
        }
    }
}

// ---------------- CSR aggregate: H[i] += sum_{e: dst=i} M[src(e)] ----------------
__global__ __launch_bounds__(256) void agg1_kernel() {
    int node = (blockIdx.x * blockDim.x + threadIdx.x) >> 5;
    if (node >= N_NODES) return;
    const int lane = threadIdx.x & 31;
    const float4* __restrict__ M = (const float4*)g_m;
    float4* __restrict__ H = (float4*)g_h1;
    int s = g_rowptr[node], e = g_rowptr[node + 1];
    float4 acc = make_float4(0.f, 0.f, 0.f, 0.f);
    for (int j = s; j < e; j++) {
        int src = g_srcs[j];
        float4 v = M[(size_t)src * 32 + lane];
        acc.x += v.x; acc.y += v.y; acc.z += v.z; acc.w += v.w;
    }
    float4 h = H[(size_t)node * 32 + lane];
    h.x += acc.x; h.y += acc.y; h.z += acc.z; h.w += acc.w;
    H[(size_t)node * 32 + lane] = h;
}

// ---------------- layer-2 aggregate fused with mean-pool + head ----------------
__global__ __launch_bounds__(256) void agg2_pool_kernel(const void* __restrict__ batch,
                                                        const float* __restrict__ Wout,
                                                        float* __restrict__ out) {
    int node = (blockIdx.x * blockDim.x + threadIdx.x) >> 5;
    if (node >= N_NODES) return;
    const int lane = threadIdx.x & 31;
    const float4* __restrict__ M = (const float4*)g_m;
    const float4* __restrict__ R = (const float4*)g_h2;   // root + bias part
    int s = g_rowptr[node], e = g_rowptr[node + 1];
    float4 acc = make_float4(0.f, 0.f, 0.f, 0.f);
    for (int j = s; j < e; j++) {
        int src = g_srcs[j];
        float4 v = M[(size_t)src * 32 + lane];
        acc.x += v.x; acc.y += v.y; acc.z += v.z; acc.w += v.w;
    }
    float4 r = R[(size_t)node * 32 + lane];
    r.x = fmaxf(r.x + acc.x, 0.f); r.y = fmaxf(r.y + acc.y, 0.f);
    r.z = fmaxf(r.z + acc.z, 0.f); r.w = fmaxf(r.w + acc.w, 0.f);
    float4 w = ((const float4*)Wout)[lane];
    float sdot = r.x * w.x + r.y * w.y + r.z * w.z + r.w * w.w;
#pragma unroll
    for (int o = 16; o; o >>= 1) sdot += __shfl_xor_sync(0xffffffffu, sdot, o);
    if (lane == 0) {
        int gidx = ld_idx(batch, node, g_is64);
        int c = g_cnt[gidx]; if (c < 1) c = 1;
        atomicAdd(&out[gidx], sdot / (float)c);
    }
}

// ---------------- misc ----------------
__global__ void init_kernel(float* __restrict__ out, const float* __restrict__ b_out) {
    int t = threadIdx.x;
    if (t < N_GRAPHS) { g_cnt[t] = 0; out[t] = b_out[0]; }
}
__global__ void count_kernel(const void* __restrict__ batch) {
    int i = blockIdx.x * blockDim.x + threadIdx.x;
    if (i < N_NODES) atomicAdd(&g_cnt[ld_idx(batch, i, g_is64)], 1);
}

// ---------------- launcher ----------------
extern "C" void kernel_launch(void* const* d_in, const int* in_sizes, int n_in,
                              void* d_out, int out_size) {
    const float* x       = (const float*)d_in[0];
    const void*  edges   = d_in[1];
    const void*  batch   = d_in[2];
    const float* W1_rel  = (const float*)d_in[3];
    const float* W1_root = (const float*)d_in[4];
    const float* b1      = (const float*)d_in[5];
    const float* W2_rel  = (const float*)d_in[6];
    const float* W2_root = (const float*)d_in[7];
    const float* b2      = (const float*)d_in[8];
    const float* W_out   = (const float*)d_in[9];
    const float* b_out   = (const float*)d_in[10];
    float* out = (float*)d_out;

    cudaFuncSetAttribute(gemm_mma, cudaFuncAttributeMaxDynamicSharedMemorySize, SMEM_BYTES);

    const dim3 gemmGrid((N_NODES + 63) / 64, 2);     // (782, 2)
    const int aggBlks = (N_NODES * 32 + 255) / 256;  // warp per node

    detect_kernel<<<1, 32>>>((const unsigned*)edges);

    // CSR build (once per launch; reused by both layers)
    zero_csr_kernel<<<(SCAN_N + 255) / 256, 256>>>();
    init_kernel<<<1, 256>>>(out, b_out);
    hist_kernel<<<(N_EDGES + 255) / 256, 256>>>(edges);
    scan1_kernel<<<SCAN_BLKS, 1024>>>();
    scan2_kernel<<<1, 32>>>();
    scan3_kernel<<<SCAN_BLKS, 1024>>>();
    fill_kernel<<<(N_EDGES + 255) / 256, 256>>>(edges);
    count_kernel<<<(N_NODES + 255) / 256, 256>>>(batch);

    gemm_mma<<<gemmGrid, 256, SMEM_BYTES>>>(x, W1_rel, W1_root, b1, 0);
    agg1_kernel<<<aggBlks, 256>>>();

    gemm_mma<<<gemmGrid, 256, SMEM_BYTES>>>(x, W2_rel, W2_root, b2, 1);
    agg2_pool_kernel<<<aggBlks, 256>>>(batch, W_out, out);
}